// round 6
// baseline (speedup 1.0000x reference)
#include <cuda_runtime.h>
#include <cstdint>

// Problem constants (from reference setup_inputs)
#define BB 16
#define TT 4096
#define DD 768
#define SS 64
#define D4 (DD / 4)          // 192 float4 lanes per row
#define OUT_VEC ((size_t)BB * 2 * SS * DD)   // 1,572,864 floats

// One block per (b, s) segment. 192 threads; thread tid owns float4 column tid.
// Token loop batched x6 (6 independent LDG.128.CS in flight; 48-reg budget keeps
// 7 CTAs/SM resident). Rep-row gather hoisted before the stream to warm L2.
__global__ __launch_bounds__(192, 7) void pooling_kernel(
    const float* __restrict__ wv,           // [B, T, D]
    const int* __restrict__ rep_ids,        // [B, S]
    const int* __restrict__ rep_mask,       // [B, S] bool marshaled as int32
    const int* __restrict__ lens,           // [B, S]
    const int* __restrict__ len_mask,       // [B, S] bool marshaled as int32
    float* __restrict__ out,                // [B, 2S, D] (+ optional [B, 2S] mask tail)
    int write_mask_tail)
{
    const int blk = blockIdx.x;             // b*S + s
    const int b = blk / SS;
    const int s = blk % SS;
    const int tid = threadIdx.x;            // 0..191

    __shared__ int sh_bounds[2];
    __shared__ float sh_cnt[192];
    __shared__ int sh_empty;

    if (tid == 0) {
        const int* lrow = lens + b * SS;
        int start = 0;
        #pragma unroll 8
        for (int i = 0; i < SS; i++) {
            int li = lrow[i];
            if (i < s) start += li;
        }
        long long endl = (long long)start + (long long)lrow[s];
        if (start < 0) start = 0;
        if (start > TT) start = TT;
        int end = (endl > TT) ? TT : (int)endl;
        if (end < start) end = start;
        sh_bounds[0] = start;
        sh_bounds[1] = end;
    }
    __syncthreads();
    const int start = sh_bounds[0];
    const int end   = sh_bounds[1];

    const float4* base = reinterpret_cast<const float4*>(wv + (size_t)b * TT * DD);

    // Rep gather first: warms L2 for the stream's opening rows and overlaps
    // its latency with the mean loop.
    int rid = rep_ids[b * SS + s];
    if (rid < 0) rid = 0;
    if (rid >= TT) rid = TT - 1;
    float4 r = __ldg(base + (size_t)rid * D4 + tid);

    const float4* p = base + (size_t)start * D4 + tid;

    float sx = 0.f, sy = 0.f, sz = 0.f, sw = 0.f;
    float cx = 0.f, cy = 0.f, cz = 0.f, cw = 0.f;

    int t = start;
    // Main loop: 6 tokens per iteration, 6 independent LDG.128.CS in flight.
    for (; t + 6 <= end; t += 6, p += 6 * D4) {
        float4 v0 = __ldcs(p);
        float4 v1 = __ldcs(p + D4);
        float4 v2 = __ldcs(p + 2 * D4);
        float4 v3 = __ldcs(p + 3 * D4);
        float4 v4 = __ldcs(p + 4 * D4);
        float4 v5 = __ldcs(p + 5 * D4);

        sx += v0.x + v1.x + v2.x + v3.x + v4.x + v5.x;
        sy += v0.y + v1.y + v2.y + v3.y + v4.y + v5.y;
        sz += v0.z + v1.z + v2.z + v3.z + v4.z + v5.z;
        sw += v0.w + v1.w + v2.w + v3.w + v4.w + v5.w;

        cx += ((v0.x != 0.f) ? 1.f : 0.f) + ((v1.x != 0.f) ? 1.f : 0.f)
            + ((v2.x != 0.f) ? 1.f : 0.f) + ((v3.x != 0.f) ? 1.f : 0.f)
            + ((v4.x != 0.f) ? 1.f : 0.f) + ((v5.x != 0.f) ? 1.f : 0.f);
        cy += ((v0.y != 0.f) ? 1.f : 0.f) + ((v1.y != 0.f) ? 1.f : 0.f)
            + ((v2.y != 0.f) ? 1.f : 0.f) + ((v3.y != 0.f) ? 1.f : 0.f)
            + ((v4.y != 0.f) ? 1.f : 0.f) + ((v5.y != 0.f) ? 1.f : 0.f);
        cz += ((v0.z != 0.f) ? 1.f : 0.f) + ((v1.z != 0.f) ? 1.f : 0.f)
            + ((v2.z != 0.f) ? 1.f : 0.f) + ((v3.z != 0.f) ? 1.f : 0.f)
            + ((v4.z != 0.f) ? 1.f : 0.f) + ((v5.z != 0.f) ? 1.f : 0.f);
        cw += ((v0.w != 0.f) ? 1.f : 0.f) + ((v1.w != 0.f) ? 1.f : 0.f)
            + ((v2.w != 0.f) ? 1.f : 0.f) + ((v3.w != 0.f) ? 1.f : 0.f)
            + ((v4.w != 0.f) ? 1.f : 0.f) + ((v5.w != 0.f) ? 1.f : 0.f);
    }
    // Tail (general correctness for lengths % 6 != 0)
    for (; t < end; t++, p += D4) {
        float4 v = __ldcs(p);
        sx += v.x; sy += v.y; sz += v.z; sw += v.w;
        cx += (v.x != 0.f) ? 1.f : 0.f;
        cy += (v.y != 0.f) ? 1.f : 0.f;
        cz += (v.z != 0.f) ? 1.f : 0.f;
        cw += (v.w != 0.f) ? 1.f : 0.f;
    }

    // Whole-segment emptiness check (seg_cnt.sum(-1) == 0)
    sh_cnt[tid] = cx + cy + cz + cw;
    __syncthreads();
    if (tid == 0) {
        float tot = 0.f;
        #pragma unroll 8
        for (int i = 0; i < 192; i++) tot += sh_cnt[i];
        sh_empty = (tot == 0.f) ? 1 : 0;
    }
    __syncthreads();
    const bool empty = (sh_empty != 0);

    const float lm = (len_mask[b * SS + s] != 0) ? 1.f : 0.f;
    const float rm = (rep_mask[b * SS + s] != 0) ? 1.f : 0.f;

    float4 o;
    if (empty) {
        // fallback to word_vectors[0, 0, :]
        float4 w0 = __ldg(reinterpret_cast<const float4*>(wv) + tid);
        o.x = w0.x * lm; o.y = w0.y * lm; o.z = w0.z * lm; o.w = w0.w * lm;
    } else {
        float dx = (cx == 0.f) ? 1.f : cx;
        float dy = (cy == 0.f) ? 1.f : cy;
        float dz = (cz == 0.f) ? 1.f : cz;
        float dw = (cw == 0.f) ? 1.f : cw;
        o.x = (sx / dx) * lm;
        o.y = (sy / dy) * lm;
        o.z = (sz / dz) * lm;
        o.w = (sw / dw) * lm;
    }
    float4* out4 = reinterpret_cast<float4*>(out);
    // mean_vec -> out[b, S + s, :]
    __stcs(&out4[((size_t)b * 2 * SS + SS + s) * D4 + tid], o);
    // rep_vec -> out[b, s, :]
    r.x *= rm; r.y *= rm; r.z *= rm; r.w *= rm;
    __stcs(&out4[((size_t)b * 2 * SS + s) * D4 + tid], r);

    // output mask tail (flattened tuple): out_tail[b, c] with c in [0, 2S)
    if (write_mask_tail) {
        float* out_tail = out + OUT_VEC;
        if (tid == 0) out_tail[b * 2 * SS + s]      = rm;   // rep mask half
        if (tid == 1) out_tail[b * 2 * SS + SS + s] = lm;   // len mask half
    }
}

extern "C" void kernel_launch(void* const* d_in, const int* in_sizes, int n_in,
                              void* d_out, int out_size)
{
    const float* wv       = (const float*)d_in[0];
    const int*   rep_ids  = (const int*)d_in[1];
    const int*   rep_mask = (const int*)d_in[2];
    const int*   lens     = (const int*)d_in[3];
    const int*   len_mask = (const int*)d_in[4];
    float* out = (float*)d_out;

    int write_mask_tail = ((size_t)out_size > OUT_VEC) ? 1 : 0;
    pooling_kernel<<<BB * SS, 192>>>(wv, rep_ids, rep_mask, lens, len_mask, out,
                                     write_mask_tail);
}